// round 15
// baseline (speedup 1.0000x reference)
#include <cuda_runtime.h>

#define N_NODES 12288
#define FDIM    32
#define NBLK    1184        // 148 SMs * 8 blocks — co-residency guaranteed
#define NTHR    256
#define NT      (NBLK * NTHR)
#define OUT_F4  ((N_NODES * (FDIM + 1)) / 4)     // 101376 float4 in d_out

// Scratch. Zero-initialized at module load; phase C re-zeros g_deg
// (graph-replay safe). g_inv / g_ya rewritten identically each launch.
__device__ __align__(16) float g_deg[N_NODES];
__device__            int   g_inv[N_NODES];   // node -> perm idx + 1 (0 = absent)
__device__ __align__(16) float g_ya [N_NODES];

// Grid barrier state (sense-reversal; g_gen monotonic across replays)
__device__ unsigned g_count = 0;
__device__ volatile unsigned g_gen = 0;

__device__ __forceinline__ void grid_barrier() {
    __syncthreads();
    if (threadIdx.x == 0) {
        __threadfence();                       // publish this block's work
        unsigned gen = g_gen;
        if (atomicAdd(&g_count, 1u) == NBLK - 1) {
            g_count = 0;
            __threadfence();
            g_gen = gen + 1;                   // release
        } else {
            while (g_gen == gen) __nanosleep(32);
        }
    }
    __syncthreads();
}

// ---------------------------------------------------------------------------
// One persistent kernel, three phases separated by grid barriers.
__global__ void __launch_bounds__(NTHR, 8)
k_fused(const int* __restrict__ ei_row,
        const int* __restrict__ ei_col,
        const float* __restrict__ attr, int nE,
        const float* __restrict__ fea,
        const int* __restrict__ perm,
        const float* __restrict__ coffe,
        const int* __restrict__ bs_ptr,
        int n_perm, int coffe_len,
        float* __restrict__ out) {
    const int gtid = blockIdx.x * NTHR + threadIdx.x;

    // ---------------- Phase A: zero d_out, degree atomics, perm scatter ----
    for (int t = gtid; t < OUT_F4; t += NT)
        ((float4*)out)[t] = make_float4(0.f, 0.f, 0.f, 0.f);

    const int nV = nE >> 1;                    // nE is even (393216)
    for (int v = gtid; v < nV; v += NT) {
        int2   r2 = ((const int2*)ei_row)[v];
        float2 a2 = ((const float2*)attr)[v];
        atomicAdd(&g_deg[r2.x], a2.x);
        atomicAdd(&g_deg[r2.y], a2.y);
    }

    for (int k = gtid; k < n_perm; k += NT) {
        int node = perm[k];
        g_inv[node] = k + 1;
        int bs        = *bs_ptr;
        int node_num  = coffe_len / bs;        // 192
        int per_batch = n_perm / bs;           // win*node_num
        int b = k / per_batch;
        int n = k % node_num;
        g_ya[node] = coffe[b * node_num + n];
    }

    grid_barrier();

    // ---------------- Phase B: edge reds straight into d_out ---------------
    // 8 threads per edge; columns absent from perm contribute zero -> skip.
    const long long totB = (long long)nE * 8;
    for (long long t = gtid; t < totB; t += NT) {
        int e = (int)(t >> 3);
        int q = (int)(t & 7);
        int c  = ei_col[e];
        int pk = g_inv[c];
        if (pk == 0) continue;

        int   r = ei_row[e];
        float s = attr[e] * rsqrtf(g_deg[c] + 1.0f);   // attr * d[c]

        float4 v = ((const float4*)(fea + (size_t)(pk - 1) * FDIM))[q];
        v.x *= s; v.y *= s; v.z *= s; v.w *= s;

        float* dst = out + (size_t)r * FDIM + q * 4;
        asm volatile("red.global.add.v4.f32 [%0], {%1, %2, %3, %4};"
                     :: "l"(dst), "f"(v.x), "f"(v.y), "f"(v.z), "f"(v.w)
                     : "memory");

        if (q == 0) {
            atomicAdd(out + (size_t)N_NODES * FDIM + r, s * g_ya[c]);
        }
    }

    grid_barrier();

    // ---------------- Phase C: in-place finalize + scratch re-zero ---------
    //   x[i]    = d[i] * (acc + d[i]*x_zero[i])   (self-loop folded)
    //   atte[i] = d[i] * (accA + d[i]*ya[i])
    // __ldcg: read accumulators from L2 (phase-A stores must not be served
    // from a stale L1 line).
    for (int t = gtid; t < N_NODES * 8; t += NT) {
        int i = t >> 3;
        int q = t & 7;
        float di = rsqrtf(g_deg[i] + 1.0f);
        int   pk = g_inv[i];

        float4 y = make_float4(0.f, 0.f, 0.f, 0.f);
        if (pk) y = ((const float4*)(fea + (size_t)(pk - 1) * FDIM))[q];

        float4* slot = (float4*)out + (size_t)i * (FDIM / 4) + q;
        float4 acc = __ldcg(slot);
        float4 o;
        o.x = di * fmaf(di, y.x, acc.x);
        o.y = di * fmaf(di, y.y, acc.y);
        o.z = di * fmaf(di, y.z, acc.z);
        o.w = di * fmaf(di, y.w, acc.w);
        *slot = o;

        if (q == 0) {
            float ya = pk ? g_ya[i] : 0.f;
            float* aslot = out + (size_t)N_NODES * FDIM + i;
            *aslot = di * fmaf(di, ya, __ldcg(aslot));
            g_deg[i] = 0.f;                    // clean for next replay
        }
    }
}

// ---------------------------------------------------------------------------
extern "C" void kernel_launch(void* const* d_in, const int* in_sizes, int n_in,
                              void* d_out, int out_size) {
    // metadata order:
    // 0: fea float32[6144,32]  1: perm int32[6144]  2: edge_index int32[2,393216]
    // 3: edge_attr float32[393216]  4: node_atte float32[1536]
    // 5: all_node_num int32[1]  6: batch_size int32[1]
    const float* fea    = (const float*)d_in[0];
    const int*   perm   = (const int*)  d_in[1];
    const int*   eidx   = (const int*)  d_in[2];
    const float* attr   = (const float*)d_in[3];
    const float* coffe  = (const float*)d_in[4];
    const int*   bs_ptr = (const int*)  d_in[6];

    const int n_perm    = in_sizes[1];
    const int nE        = in_sizes[3];
    const int coffe_len = in_sizes[4];
    const int* ei_row = eidx;
    const int* ei_col = eidx + nE;

    float* out = (float*)d_out;
    (void)out_size; (void)n_in;

    k_fused<<<NBLK, NTHR>>>(ei_row, ei_col, attr, nE, fea, perm, coffe,
                            bs_ptr, n_perm, coffe_len, out);
}

// round 17
// speedup vs baseline: 1.0023x; 1.0023x over previous
#include <cuda_runtime.h>

#define N_NODES 12288
#define FDIM    32
#define OUT_F4  ((N_NODES * (FDIM + 1)) / 4)    // 101376 float4 in d_out

// Scratch. Zero-initialized at module load; k_final re-zeros g_deg
// (graph-replay safe). g_inv / g_ya rewritten identically each launch.
__device__ __align__(16) float g_deg[N_NODES];
__device__            int   g_inv[N_NODES];     // node -> perm idx + 1 (0 = absent)
__device__ __align__(16) float g_ya [N_NODES];

// ---------------------------------------------------------------------------
// K_front: three independent block ranges.
//   [0, ZB):        zero d_out
//   [ZB, ZB+EB):    deg[r] += attr[e], 2 edges/thread
//   [ZB+EB, +SB):   inverse-perm table + attention-coefficient scatter
__global__ void k_front(float* __restrict__ out,
                        const int* __restrict__ ei_row,
                        const float* __restrict__ attr, int nE,
                        const int* __restrict__ perm,
                        const float* __restrict__ coffe,
                        const int* __restrict__ bs_ptr,
                        int n_perm, int coffe_len, int ZB, int EB) {
    if (blockIdx.x < ZB) {
        int t = blockIdx.x * blockDim.x + threadIdx.x;
        if (t < OUT_F4)
            ((float4*)out)[t] = make_float4(0.f, 0.f, 0.f, 0.f);
    } else if (blockIdx.x < ZB + EB) {
        int v = (blockIdx.x - ZB) * blockDim.x + threadIdx.x;  // pair index
        int e = v * 2;
        if (e + 1 < nE) {
            int2   r2 = ((const int2*)ei_row)[v];
            float2 a2 = ((const float2*)attr)[v];
            atomicAdd(&g_deg[r2.x], a2.x);
            atomicAdd(&g_deg[r2.y], a2.y);
        } else if (e < nE) {
            atomicAdd(&g_deg[ei_row[e]], attr[e]);
        }
    } else {
        int k = (blockIdx.x - ZB - EB) * blockDim.x + threadIdx.x;
        if (k < n_perm) {
            int node = perm[k];
            g_inv[node] = k + 1;
            int bs        = *bs_ptr;
            int node_num  = coffe_len / bs;     // 192
            int per_batch = n_perm / bs;        // win*node_num
            int b = k / per_batch;
            int n = k % node_num;
            g_ya[node] = coffe[b * node_num + n];
        }
    }
}

// ---------------------------------------------------------------------------
// K_edge, warp-cooperative: each warp owns 4 edges. Lanes 0-3 do the per-edge
// scalar work ONCE; shfl broadcasts (pk, r, s, s*ya) to the 8-lane slice
// groups that do the float4 gather + red.v4 into d_out.
// ALL shuffles execute before ANY lane can exit (full-mask shfl with exited
// lanes is UB -- that was the R16 bug).
__global__ void k_edge(const int* __restrict__ ei_row,
                       const int* __restrict__ ei_col,
                       const float* __restrict__ attr,
                       const float* __restrict__ fea,
                       float* __restrict__ out, int nE) {
    int gtid = blockIdx.x * blockDim.x + threadIdx.x;
    int lane = threadIdx.x & 31;
    int base_e = (gtid >> 5) * 4;
    if (base_e >= nE) return;          // whole warp exits together

    int   pk = 0, r = 0;
    float s = 0.f, sya = 0.f;
    if (lane < 4) {
        int e = base_e + lane;
        int c = ei_col[e];
        pk = g_inv[c];
        if (pk) {
            r   = ei_row[e];
            s   = attr[e] * rsqrtf(g_deg[c] + 1.0f);   // attr * d[c]
            sya = s * g_ya[c];
        }
    }

    int src = lane >> 3;               // which of the 4 edges this lane serves
    int q   = lane & 7;                // float4 slice within the edge
    // All warp-collective shuffles BEFORE any early-out.
    int   pk_e  = __shfl_sync(0xffffffffu, pk,  src);
    int   r_e   = __shfl_sync(0xffffffffu, r,   src);
    float s_e   = __shfl_sync(0xffffffffu, s,   src);
    float sya_e = __shfl_sync(0xffffffffu, sya, src);

    if (pk_e == 0) return;             // inactive column: zero contribution

    float4 v = ((const float4*)(fea + (size_t)(pk_e - 1) * FDIM))[q];
    v.x *= s_e; v.y *= s_e; v.z *= s_e; v.w *= s_e;

    float* dst = out + (size_t)r_e * FDIM + q * 4;
    asm volatile("red.global.add.v4.f32 [%0], {%1, %2, %3, %4};"
                 :: "l"(dst), "f"(v.x), "f"(v.y), "f"(v.z), "f"(v.w)
                 : "memory");

    if (q == 0) {
        atomicAdd(out + (size_t)N_NODES * FDIM + r_e, sya_e);
    }
}

// ---------------------------------------------------------------------------
// K_final: in-place scale of d_out:
//   x[i]    = d[i] * (acc + d[i]*x_zero[i])   (self-loop folded)
//   atte[i] = d[i] * (accA + d[i]*ya[i])
// Re-zeros g_deg for the next replay.
__global__ void k_final(const float* __restrict__ fea, float* __restrict__ out) {
    int t = blockIdx.x * blockDim.x + threadIdx.x;
    int i = t >> 3;
    int q = t & 7;
    if (i >= N_NODES) return;
    float di = rsqrtf(g_deg[i] + 1.0f);
    int   pk = g_inv[i];

    float4 y = make_float4(0.f, 0.f, 0.f, 0.f);
    if (pk) y = ((const float4*)(fea + (size_t)(pk - 1) * FDIM))[q];

    float4* slot = (float4*)out + (size_t)i * (FDIM / 4) + q;
    float4 acc = *slot;
    float4 o;
    o.x = di * fmaf(di, y.x, acc.x);
    o.y = di * fmaf(di, y.y, acc.y);
    o.z = di * fmaf(di, y.z, acc.z);
    o.w = di * fmaf(di, y.w, acc.w);
    *slot = o;

    if (q == 0) {
        float ya = pk ? g_ya[i] : 0.f;
        float* aslot = out + (size_t)N_NODES * FDIM + i;
        *aslot = di * fmaf(di, ya, *aslot);
        g_deg[i] = 0.f;
    }
}

// ---------------------------------------------------------------------------
extern "C" void kernel_launch(void* const* d_in, const int* in_sizes, int n_in,
                              void* d_out, int out_size) {
    // metadata order:
    // 0: fea float32[6144,32]  1: perm int32[6144]  2: edge_index int32[2,393216]
    // 3: edge_attr float32[393216]  4: node_atte float32[1536]
    // 5: all_node_num int32[1]  6: batch_size int32[1]
    const float* fea    = (const float*)d_in[0];
    const int*   perm   = (const int*)  d_in[1];
    const int*   eidx   = (const int*)  d_in[2];
    const float* attr   = (const float*)d_in[3];
    const float* coffe  = (const float*)d_in[4];
    const int*   bs_ptr = (const int*)  d_in[6];

    const int n_perm    = in_sizes[1];
    const int nE        = in_sizes[3];
    const int coffe_len = in_sizes[4];
    const int* ei_row = eidx;
    const int* ei_col = eidx + nE;

    float* out = (float*)d_out;
    (void)out_size; (void)n_in;

    const int T  = 256;
    const int ZB = (OUT_F4 + T - 1) / T;             // zero-out blocks
    const int nV = (nE + 1) / 2;
    const int EB = (nV + T - 1) / T;                 // edge-degree blocks
    const int SB = (n_perm + T - 1) / T;             // perm-scatter blocks

    k_front<<<ZB + EB + SB, T>>>(out, ei_row, attr, nE, perm, coffe, bs_ptr,
                                 n_perm, coffe_len, ZB, EB);

    {
        // one warp per 4 edges -> nE * 8 threads
        long long nt = (long long)nE * 8;
        k_edge<<<(unsigned)((nt + T - 1) / T), T>>>(ei_row, ei_col, attr, fea,
                                                    out, nE);
    }

    k_final<<<(N_NODES * 8 + T - 1) / T, T>>>(fea, out);
}